// round 3
// baseline (speedup 1.0000x reference)
#include <cuda_runtime.h>
#include <cstdint>

#define T_STEPS 1024
#define B_      64
#define D_      512
#define H_      512
#define K_TOT   1024

#define G_CTAS   64
#define S_COLS   8
#define NTHREADS 128
#define KC       64
#define NCHUNK   (K_TOT / KC)
#define KS_PER_CHUNK (KC / 8)

#define WP_FLOATS 32768
#define AS_STRIDE 68
#define AS_BUF    (B_ * AS_STRIDE)
#define SMEM_FLOATS (WP_FLOATS + 2 * AS_BUF)
#define SMEM_BYTES  (SMEM_FLOATS * 4)

__device__ float g_xtf[(size_t)T_STEPS * B_ * D_];
__device__ float g_hbuf[2][B_ * H_];
__device__ unsigned g_arrive;
__device__ volatile unsigned g_phase;

__device__ __forceinline__ float tf32r(float x) {
    unsigned r;
    asm("cvt.rna.tf32.f32 %0, %1;" : "=r"(r) : "f"(x));
    return __uint_as_float(r);
}
__device__ __forceinline__ float sigm_(float x) {
    return __fdividef(1.0f, 1.0f + __expf(-x));
}
__device__ __forceinline__ float tanh_(float x) {
    float a = fabsf(x);
    float e = __expf(-2.0f * a);
    float r = __fdividef(1.0f - e, 1.0f + e);
    return copysignf(r, x);
}

__global__ void lstm_init(const float4* __restrict__ x4, const float* __restrict__ h0) {
    unsigned tid  = blockIdx.x * blockDim.x + threadIdx.x;
    unsigned nthr = gridDim.x * blockDim.x;
    if (tid == 0) { g_arrive = 0; g_phase = 0; }
    for (unsigned i = tid; i < B_ * H_; i += nthr)
        g_hbuf[0][i] = tf32r(h0[i]);
    float4* xo = reinterpret_cast<float4*>(g_xtf);
    const size_t n4 = (size_t)T_STEPS * B_ * D_ / 4;
    for (size_t i = tid; i < n4; i += nthr) {
        float4 v = x4[i];
        v.x = tf32r(v.x); v.y = tf32r(v.y); v.z = tf32r(v.z); v.w = tf32r(v.w);
        xo[i] = v;
    }
}

__global__ void __launch_bounds__(NTHREADS, 1)
lstm_persist(const float* __restrict__ c0,
             const float* __restrict__ Wii, const float* __restrict__ Whi, const float* __restrict__ bi,
             const float* __restrict__ Wif, const float* __restrict__ Whf, const float* __restrict__ bf,
             const float* __restrict__ Wig, const float* __restrict__ Whg, const float* __restrict__ bg,
             const float* __restrict__ Wio, const float* __restrict__ Who, const float* __restrict__ bo,
             float* __restrict__ out)
{
    extern __shared__ float smem[];
    float* Wp = smem;
    float* As = smem + WP_FLOATS;

    const int tid  = threadIdx.x;
    const int wid  = tid >> 5;
    const int lane = tid & 31;
    const int g    = lane >> 2;
    const int t    = lane & 3;
    const int cta  = blockIdx.x;

    // one-time: stage weight slice, tf32-rounded, permuted to B-fragment order
    {
        const float* Wx[4] = {Wii, Wif, Wig, Wio};
        const float* Wh[4] = {Whi, Whf, Whg, Who};
        for (int e = tid; e < WP_FLOATS; e += NTHREADS) {
            int j   = e & 1;
            int ln  = (e >> 1) & 31;
            int nt  = (e >> 6) & 3;
            int ksg = e >> 8;
            int jj  = ln >> 2;
            int k   = ksg * 8 + (ln & 3) + 4 * j;
            int col = cta * S_COLS + jj;
            float v = (k < D_) ? Wx[nt][k * H_ + col]
                               : Wh[nt][(k - D_) * H_ + col];
            Wp[e] = tf32r(v);
        }
    }

    const int col0 = cta * S_COLS + 2 * t;
    const int col1 = col0 + 1;
    const int rb0  = wid * 16 + g;
    const int rb1  = rb0 + 8;
    const float bi0 = bi[col0], bi1 = bi[col1];
    const float bf0 = bf[col0], bf1 = bf[col1];
    const float bg0 = bg[col0], bg1 = bg[col1];
    const float bo0 = bo[col0], bo1 = bo[col1];
    float creg[4];
    creg[0] = c0[rb0 * H_ + col0];
    creg[1] = c0[rb0 * H_ + col1];
    creg[2] = c0[rb1 * H_ + col0];
    creg[3] = c0[rb1 * H_ + col1];

    __syncthreads();

    const unsigned* WpU = reinterpret_cast<const unsigned*>(Wp);

    for (int step = 0; step < T_STEPS; ++step) {
        const float* hprev = g_hbuf[step & 1];
        float*       hnext = g_hbuf[(step + 1) & 1];
        const float* xt    = g_xtf + (size_t)step * B_ * D_;

        float acc[4][4] = {};

        // stage chunk 0 (x only: columns 0..63)
        #pragma unroll
        for (int i2 = 0; i2 < 8; ++i2) {
            int q = i2 * NTHREADS + tid;
            int row = q >> 4, f4 = q & 15;
            float4 v = __ldg(reinterpret_cast<const float4*>(xt + row * D_ + f4 * 4));
            *reinterpret_cast<float4*>(As + row * AS_STRIDE + f4 * 4) = v;
        }
        __syncthreads();

        float4 pre[8];
        #pragma unroll 1
        for (int cc = 0; cc < NCHUNK; ++cc) {
            if (cc + 1 < NCHUNK) {
                int koff = (cc + 1) * KC;
                if (koff < D_) {
                    const float* src = xt + koff;
                    #pragma unroll
                    for (int i2 = 0; i2 < 8; ++i2) {
                        int q = i2 * NTHREADS + tid;
                        int row = q >> 4, f4 = q & 15;
                        pre[i2] = __ldg(reinterpret_cast<const float4*>(src + row * D_ + f4 * 4));
                    }
                } else {
                    // h buffer: bypass L1 (stale across grid barrier)
                    const float* src = hprev + (koff - D_);
                    #pragma unroll
                    for (int i2 = 0; i2 < 8; ++i2) {
                        int q = i2 * NTHREADS + tid;
                        int row = q >> 4, f4 = q & 15;
                        pre[i2] = __ldcg(reinterpret_cast<const float4*>(src + row * H_ + f4 * 4));
                    }
                }
            }

            const float* Ab = As + (cc & 1) * AS_BUF;
            #pragma unroll
            for (int ks = 0; ks < KS_PER_CHUNK; ++ks) {
                const int kb = ks * 8;
                unsigned a0 = __float_as_uint(Ab[(wid * 16 + g)     * AS_STRIDE + kb + t]);
                unsigned a1 = __float_as_uint(Ab[(wid * 16 + g + 8) * AS_STRIDE + kb + t]);
                unsigned a2 = __float_as_uint(Ab[(wid * 16 + g)     * AS_STRIDE + kb + t + 4]);
                unsigned a3 = __float_as_uint(Ab[(wid * 16 + g + 8) * AS_STRIDE + kb + t + 4]);
                const int ksg = cc * KS_PER_CHUNK + ks;
                #pragma unroll
                for (int nt = 0; nt < 4; ++nt) {
                    uint2 b2 = *reinterpret_cast<const uint2*>(
                        WpU + ((size_t)(ksg * 4 + nt) * 32 + lane) * 2);
                    asm volatile(
                        "mma.sync.aligned.m16n8k8.row.col.f32.tf32.tf32.f32 "
                        "{%0,%1,%2,%3}, {%4,%5,%6,%7}, {%8,%9}, {%0,%1,%2,%3};"
                        : "+f"(acc[nt][0]), "+f"(acc[nt][1]),
                          "+f"(acc[nt][2]), "+f"(acc[nt][3])
                        : "r"(a0), "r"(a1), "r"(a2), "r"(a3),
                          "r"(b2.x), "r"(b2.y));
                }
            }

            if (cc + 1 < NCHUNK) {
                float* An = As + ((cc + 1) & 1) * AS_BUF;
                #pragma unroll
                for (int i2 = 0; i2 < 8; ++i2) {
                    int q = i2 * NTHREADS + tid;
                    int row = q >> 4, f4 = q & 15;
                    *reinterpret_cast<float4*>(An + row * AS_STRIDE + f4 * 4) = pre[i2];
                }
            }
            __syncthreads();
        }

        // epilogue: gates -> cell update -> h
        #pragma unroll
        for (int ci = 0; ci < 4; ++ci) {
            const int rb  = (ci >= 2) ? rb1 : rb0;
            const int col = (ci & 1) ? col1 : col0;
            float pi = acc[0][ci] + ((ci & 1) ? bi1 : bi0);
            float pf = acc[1][ci] + ((ci & 1) ? bf1 : bf0);
            float pg = acc[2][ci] + ((ci & 1) ? bg1 : bg0);
            float po = acc[3][ci] + ((ci & 1) ? bo1 : bo0);
            float iv = sigm_(pi);
            float fv = sigm_(pf);
            float gv = tanh_(pg);
            float ov = sigm_(po);
            float c  = fv * creg[ci] + iv * gv;
            creg[ci] = c;
            float h  = ov * tanh_(c);
            hnext[rb * H_ + col] = tf32r(h);
            if (step == T_STEPS - 1) {
                out[rb * H_ + col]           = h;
                out[B_ * H_ + rb * H_ + col] = c;
            }
        }

        // grid barrier
        __syncthreads();
        if (tid == 0) {
            __threadfence();
            unsigned old = atomicInc(&g_arrive, G_CTAS - 1);
            if (old == G_CTAS - 1) {
                g_phase = (unsigned)(step + 1);
            } else {
                while (g_phase < (unsigned)(step + 1)) { }
            }
            __threadfence();
        }
        __syncthreads();
    }
}

extern "C" void kernel_launch(void* const* d_in, const int* in_sizes, int n_in,
                              void* d_out, int out_size)
{
    const float* x   = (const float*)d_in[0];
    const float* h0  = (const float*)d_in[1];
    const float* c0  = (const float*)d_in[2];
    const float* Wii = (const float*)d_in[3];
    const float* Whi = (const float*)d_in[4];
    const float* bi  = (const float*)d_in[5];
    const float* Wif = (const float*)d_in[6];
    const float* Whf = (const float*)d_in[7];
    const float* bf  = (const float*)d_in[8];
    const float* Wig = (const float*)d_in[9];
    const float* Whg = (const float*)d_in[10];
    const float* bg  = (const float*)d_in[11];
    const float* Wio = (const float*)d_in[12];
    const float* Who = (const float*)d_in[13];
    const float* bo  = (const float*)d_in[14];
    float* out = (float*)d_out;

    static int smem_set = 0;
    if (!smem_set) {
        cudaFuncSetAttribute(lstm_persist,
                             cudaFuncAttributeMaxDynamicSharedMemorySize, SMEM_BYTES);
        smem_set = 1;
    }

    lstm_init<<<1024, 256>>>(reinterpret_cast<const float4*>(x), h0);
    lstm_persist<<<G_CTAS, NTHREADS, SMEM_BYTES>>>(
        c0, Wii, Whi, bi, Wif, Whf, bf, Wig, Whg, bg, Wio, Who, bo, out);
}

// round 4
// speedup vs baseline: 1.4777x; 1.4777x over previous
#include <cuda_runtime.h>
#include <cstdint>

#define T_STEPS 1024
#define B_      64
#define D_      512
#define H_      512

// ---------------- persistent kernel config --------------------
#define G_CTAS   64
#define S_COLS   8          // H-columns per CTA
#define NTHREADS 128
#define KSTEPS   (H_ / 8)   // 64 mma k-steps over h
#define KS_HALF  (KSTEPS/2) // 32 per chunk

#define WP_FLOATS (KSTEPS * 4 * 32 * 2)   // 16384 floats = 64 KB
#define AS_STRIDE 260
#define AS_BUF    (B_ * AS_STRIDE)        // 16640 floats (chunk = 64 rows x 256 k)
#define SMEM_FLOATS (WP_FLOATS + 2 * AS_BUF)
#define SMEM_BYTES  (SMEM_FLOATS * 4)     // 198656 B

// ---------------- gemm kernel config --------------------------
#define GM_AS   (128 * 36)   // 4608 floats per A buffer
#define GM_BS   (32 * 72)    // 2304 floats per B buffer
#define GM_SMEM ((2 * GM_AS + 2 * GM_BS) * 4)  // 55296 B

// ---------------- device globals ------------------------------
__device__ float    g_xp[(size_t)T_STEPS * B_ * 4 * H_];  // x_proj (+bias), 512 MB
__device__ float    g_hbuf[2][B_ * H_];
__device__ unsigned g_arrive;
__device__ volatile unsigned g_phase;

// ---------------- helpers -------------------------------------
__device__ __forceinline__ float tf32r(float x) {
    unsigned r;
    asm("cvt.rna.tf32.f32 %0, %1;" : "=r"(r) : "f"(x));
    return __uint_as_float(r);
}
__device__ __forceinline__ float sigm_(float x) {
    return __fdividef(1.0f, 1.0f + __expf(-x));
}
__device__ __forceinline__ float tanh_(float x) {
    float a = fabsf(x);
    float e = __expf(-2.0f * a);
    float r = __fdividef(1.0f - e, 1.0f + e);
    return copysignf(r, x);
}
__device__ __forceinline__ void mma8(float* acc, unsigned a0, unsigned a1,
                                     unsigned a2, unsigned a3,
                                     unsigned b0, unsigned b1) {
    asm volatile(
        "mma.sync.aligned.m16n8k8.row.col.f32.tf32.tf32.f32 "
        "{%0,%1,%2,%3}, {%4,%5,%6,%7}, {%8,%9}, {%0,%1,%2,%3};"
        : "+f"(acc[0]), "+f"(acc[1]), "+f"(acc[2]), "+f"(acc[3])
        : "r"(a0), "r"(a1), "r"(a2), "r"(a3), "r"(b0), "r"(b1));
}
__device__ __forceinline__ void cp16(unsigned dst, const void* src) {
    asm volatile("cp.async.cg.shared.global [%0], [%1], 16;\n"
                 :: "r"(dst), "l"(src) : "memory");
}

// ---------------- init: barrier flags + h0 --------------------
__global__ void lstm_init(const float* __restrict__ h0) {
    unsigned tid = blockIdx.x * blockDim.x + threadIdx.x;
    if (tid == 0) { g_arrive = 0; g_phase = 0; }
    unsigned nthr = gridDim.x * blockDim.x;
    for (unsigned i = tid; i < B_ * H_; i += nthr)
        g_hbuf[0][i] = tf32r(h0[i]);
}

// ---------------- x-projection GEMM ---------------------------
// C[M=65536, N=2048] = tf32(x[M,512]) * tf32(Wcat[512,2048]) + bias
// grid = (32 n-tiles, 512 m-tiles), CTA tile 128x64, 256 threads (8 warps 4x2)
__global__ void __launch_bounds__(256)
xproj_gemm(const float* __restrict__ x,
           const float* __restrict__ Wii, const float* __restrict__ Wif,
           const float* __restrict__ Wig, const float* __restrict__ Wio,
           const float* __restrict__ bi,  const float* __restrict__ bf,
           const float* __restrict__ bg,  const float* __restrict__ bo)
{
    extern __shared__ float sm[];
    float* As = sm;                 // 2 x 128 x 36
    float* Bs = sm + 2 * GM_AS;     // 2 x 32 x 72

    const int tid  = threadIdx.x;
    const int lane = tid & 31;
    const int wid  = tid >> 5;
    const int wm   = wid & 3;       // m32 block
    const int wn   = wid >> 2;      // n32 block
    const int g    = lane >> 2;
    const int t    = lane & 3;

    const int nb = blockIdx.x * 64;
    const int mb = blockIdx.y * 128;
    const int gate = nb >> 9;
    const int colb = nb & 511;

    const float* Wg = (gate == 0) ? Wii : (gate == 1) ? Wif : (gate == 2) ? Wig : Wio;
    const float* bv = (gate == 0) ? bi  : (gate == 1) ? bf  : (gate == 2) ? bg  : bo;

    // acc init with bias
    float acc[2][4][4];
    #pragma unroll
    for (int nt4 = 0; nt4 < 4; ++nt4) {
        float b0 = bv[colb + wn * 32 + nt4 * 8 + 2 * t];
        float b1 = bv[colb + wn * 32 + nt4 * 8 + 2 * t + 1];
        #pragma unroll
        for (int mt = 0; mt < 2; ++mt) {
            acc[mt][nt4][0] = b0; acc[mt][nt4][1] = b1;
            acc[mt][nt4][2] = b0; acc[mt][nt4][3] = b1;
        }
    }

    float4 ra[4], rb[2];
    auto ldAB = [&](int it) {
        #pragma unroll
        for (int i = 0; i < 4; ++i) {
            int idx = tid + i * 256;
            int row = idx >> 3, j4 = idx & 7;
            ra[i] = *reinterpret_cast<const float4*>(
                x + (size_t)(mb + row) * 512 + it * 32 + j4 * 4);
        }
        #pragma unroll
        for (int i = 0; i < 2; ++i) {
            int idx = tid + i * 256;
            int kr = idx >> 4, j4 = idx & 15;
            rb[i] = *reinterpret_cast<const float4*>(
                Wg + (size_t)(it * 32 + kr) * 512 + colb + j4 * 4);
        }
    };
    auto stAB = [&](int buf) {
        #pragma unroll
        for (int i = 0; i < 4; ++i) {
            int idx = tid + i * 256;
            int row = idx >> 3, j4 = idx & 7;
            float4 v = ra[i];
            v.x = tf32r(v.x); v.y = tf32r(v.y); v.z = tf32r(v.z); v.w = tf32r(v.w);
            *reinterpret_cast<float4*>(As + buf * GM_AS + row * 36 + j4 * 4) = v;
        }
        #pragma unroll
        for (int i = 0; i < 2; ++i) {
            int idx = tid + i * 256;
            int kr = idx >> 4, j4 = idx & 15;
            float4 v = rb[i];
            v.x = tf32r(v.x); v.y = tf32r(v.y); v.z = tf32r(v.z); v.w = tf32r(v.w);
            *reinterpret_cast<float4*>(Bs + buf * GM_BS + kr * 72 + j4 * 4) = v;
        }
    };

    ldAB(0);
    stAB(0);
    __syncthreads();

    #pragma unroll 1
    for (int it = 0; it < 16; ++it) {
        if (it < 15) ldAB(it + 1);
        const float* Ab = As + (it & 1) * GM_AS;
        const float* Bb = Bs + (it & 1) * GM_BS;
        #pragma unroll
        for (int ks = 0; ks < 4; ++ks) {
            const int kb = ks * 8;
            unsigned a[2][4], b[4][2];
            #pragma unroll
            for (int mt = 0; mt < 2; ++mt) {
                int rowb = wm * 32 + mt * 16;
                a[mt][0] = __float_as_uint(Ab[(rowb + g)     * 36 + kb + t]);
                a[mt][1] = __float_as_uint(Ab[(rowb + g + 8) * 36 + kb + t]);
                a[mt][2] = __float_as_uint(Ab[(rowb + g)     * 36 + kb + t + 4]);
                a[mt][3] = __float_as_uint(Ab[(rowb + g + 8) * 36 + kb + t + 4]);
            }
            #pragma unroll
            for (int nt4 = 0; nt4 < 4; ++nt4) {
                int cb = wn * 32 + nt4 * 8 + g;
                b[nt4][0] = __float_as_uint(Bb[(kb + t)     * 72 + cb]);
                b[nt4][1] = __float_as_uint(Bb[(kb + t + 4) * 72 + cb]);
            }
            #pragma unroll
            for (int mt = 0; mt < 2; ++mt)
                #pragma unroll
                for (int nt4 = 0; nt4 < 4; ++nt4)
                    mma8(acc[mt][nt4], a[mt][0], a[mt][1], a[mt][2], a[mt][3],
                         b[nt4][0], b[nt4][1]);
        }
        if (it < 15) {
            stAB((it + 1) & 1);
            __syncthreads();
        }
    }

    // store to g_xp
    #pragma unroll
    for (int mt = 0; mt < 2; ++mt) {
        #pragma unroll
        for (int nt4 = 0; nt4 < 4; ++nt4) {
            int row0 = mb + wm * 32 + mt * 16 + g;
            int col  = nb + wn * 32 + nt4 * 8 + 2 * t;
            *reinterpret_cast<float2*>(g_xp + (size_t)row0 * 2048 + col) =
                make_float2(acc[mt][nt4][0], acc[mt][nt4][1]);
            *reinterpret_cast<float2*>(g_xp + (size_t)(row0 + 8) * 2048 + col) =
                make_float2(acc[mt][nt4][2], acc[mt][nt4][3]);
        }
    }
}

// ---------------- persistent LSTM kernel (K = 512, h only) ----
__global__ void __launch_bounds__(NTHREADS, 1)
lstm_persist(const float* __restrict__ c0,
             const float* __restrict__ Whi, const float* __restrict__ Whf,
             const float* __restrict__ Whg, const float* __restrict__ Who,
             float* __restrict__ out)
{
    extern __shared__ float smem[];
    float* Wp = smem;
    float* Asb = smem + WP_FLOATS;

    const int tid  = threadIdx.x;
    const int wid  = tid >> 5;
    const int lane = tid & 31;
    const int g    = lane >> 2;
    const int t    = lane & 3;
    const int cta  = blockIdx.x;

    unsigned as_u32;
    {
        unsigned base = (unsigned)__cvta_generic_to_shared(Asb);
        as_u32 = base;
    }

    // one-time: stage recurrent weight slice, tf32, B-fragment order
    {
        const float* Wh[4] = {Whi, Whf, Whg, Who};
        for (int e = tid; e < WP_FLOATS; e += NTHREADS) {
            int j   = e & 1;
            int ln  = (e >> 1) & 31;
            int nt  = (e >> 6) & 3;
            int ksg = e >> 8;
            int jj  = ln >> 2;
            int k   = ksg * 8 + (ln & 3) + 4 * j;
            int col = cta * S_COLS + jj;
            Wp[e] = tf32r(Wh[nt][k * H_ + col]);
        }
    }

    const int col0 = cta * S_COLS + 2 * t;
    const int rb0  = wid * 16 + g;
    const int rb1  = rb0 + 8;
    float creg[4];
    creg[0] = c0[rb0 * H_ + col0];
    creg[1] = c0[rb0 * H_ + col0 + 1];
    creg[2] = c0[rb1 * H_ + col0];
    creg[3] = c0[rb1 * H_ + col0 + 1];

    __syncthreads();

    const unsigned* WpU = reinterpret_cast<const unsigned*>(Wp);

    for (int step = 0; step < T_STEPS; ++step) {
        const float* hprev = g_hbuf[step & 1];
        float*       hnext = g_hbuf[(step + 1) & 1];
        const float* xpt   = g_xp + (size_t)step * B_ * 2048;

        // issue both chunk copies (h[0:256] -> buf0, h[256:512] -> buf1)
        #pragma unroll 1
        for (int c = 0; c < 2; ++c) {
            #pragma unroll
            for (int i = 0; i < 32; ++i) {
                int idx = tid + i * NTHREADS;
                int row = idx >> 6, p = idx & 63;
                cp16(as_u32 + (unsigned)(c * AS_BUF + row * AS_STRIDE + p * 4) * 4u,
                     hprev + row * H_ + c * 256 + p * 4);
            }
            asm volatile("cp.async.commit_group;\n" ::: "memory");
        }

        // acc init from x_proj (bias already folded in)
        float acc[4][4];
        #pragma unroll
        for (int nt = 0; nt < 4; ++nt) {
            float2 v0 = *reinterpret_cast<const float2*>(
                xpt + (size_t)rb0 * 2048 + nt * 512 + col0);
            float2 v1 = *reinterpret_cast<const float2*>(
                xpt + (size_t)rb1 * 2048 + nt * 512 + col0);
            acc[nt][0] = v0.x; acc[nt][1] = v0.y;
            acc[nt][2] = v1.x; acc[nt][3] = v1.y;
        }

        asm volatile("cp.async.wait_group 1;\n" ::: "memory");
        __syncthreads();

        #pragma unroll 1
        for (int half = 0; half < 2; ++half) {
            const float* Ab = Asb + half * AS_BUF;
            #pragma unroll 4
            for (int ks = 0; ks < KS_HALF; ++ks) {
                const int kb = ks * 8;
                unsigned a0 = __float_as_uint(Ab[rb0 * AS_STRIDE + kb + t]);
                unsigned a1 = __float_as_uint(Ab[rb1 * AS_STRIDE + kb + t]);
                unsigned a2 = __float_as_uint(Ab[rb0 * AS_STRIDE + kb + t + 4]);
                unsigned a3 = __float_as_uint(Ab[rb1 * AS_STRIDE + kb + t + 4]);
                const int ksg = half * KS_HALF + ks;
                #pragma unroll
                for (int nt = 0; nt < 4; ++nt) {
                    uint2 b2 = *reinterpret_cast<const uint2*>(
                        WpU + ((size_t)(ksg * 4 + nt) * 32 + lane) * 2);
                    mma8(acc[nt], a0, a1, a2, a3, b2.x, b2.y);
                }
            }
            if (half == 0) {
                asm volatile("cp.async.wait_group 0;\n" ::: "memory");
                __syncthreads();
            }
        }

        // epilogue: gates -> cell update -> h
        #pragma unroll
        for (int ci = 0; ci < 4; ++ci) {
            const int rb  = (ci >= 2) ? rb1 : rb0;
            const int col = col0 + (ci & 1);
            float iv = sigm_(acc[0][ci]);
            float fv = sigm_(acc[1][ci]);
            float gv = tanh_(acc[2][ci]);
            float ov = sigm_(acc[3][ci]);
            float c  = fv * creg[ci] + iv * gv;
            creg[ci] = c;
            float h  = ov * tanh_(c);
            hnext[rb * H_ + col] = tf32r(h);
            if (step == T_STEPS - 1) {
                out[rb * H_ + col]           = h;
                out[B_ * H_ + rb * H_ + col] = c;
            }
        }

        // grid barrier
        __syncthreads();
        if (tid == 0) {
            __threadfence();
            unsigned old = atomicInc(&g_arrive, G_CTAS - 1);
            if (old == G_CTAS - 1) {
                g_phase = (unsigned)(step + 1);
            } else {
                while (g_phase < (unsigned)(step + 1)) { }
            }
            __threadfence();
        }
        __syncthreads();
    }
}

// ---------------- launch --------------------------------------
extern "C" void kernel_launch(void* const* d_in, const int* in_sizes, int n_in,
                              void* d_out, int out_size)
{
    const float* x   = (const float*)d_in[0];
    const float* h0  = (const float*)d_in[1];
    const float* c0  = (const float*)d_in[2];
    const float* Wii = (const float*)d_in[3];
    const float* Whi = (const float*)d_in[4];
    const float* bi  = (const float*)d_in[5];
    const float* Wif = (const float*)d_in[6];
    const float* Whf = (const float*)d_in[7];
    const float* bf  = (const float*)d_in[8];
    const float* Wig = (const float*)d_in[9];
    const float* Whg = (const float*)d_in[10];
    const float* bg  = (const float*)d_in[11];
    const float* Wio = (const float*)d_in[12];
    const float* Who = (const float*)d_in[13];
    const float* bo  = (const float*)d_in[14];
    float* out = (float*)d_out;

    static int attr_set = 0;
    if (!attr_set) {
        cudaFuncSetAttribute(lstm_persist,
                             cudaFuncAttributeMaxDynamicSharedMemorySize, SMEM_BYTES);
        cudaFuncSetAttribute(xproj_gemm,
                             cudaFuncAttributeMaxDynamicSharedMemorySize, GM_SMEM);
        attr_set = 1;
    }

    lstm_init<<<64, 256>>>(h0);
    xproj_gemm<<<dim3(32, 512), 256, GM_SMEM>>>(x, Wii, Wif, Wig, Wio,
                                                bi, bf, bg, bo);
    lstm_persist<<<G_CTAS, NTHREADS, SMEM_BYTES>>>(c0, Whi, Whf, Whg, Who, out);
}